// round 13
// baseline (speedup 1.0000x reference)
#include <cuda_runtime.h>
#include <cstdint>

// ---------------------------------------------------------------------------
// RGCN (2-layer bipartite GraphConv, norm='both') for fixed shapes:
//   N_A=50000, N_B=10000, E=300000, IN_F=HID=256, OUT=128
// Pipeline per call (all on default stream, graph-capturable):
//   degrees (atomics) -> row scales -> CSR-by-dst (scan + cursor fill)
//   GEMM1 (row-scaled)  -> agg+bias+relu   (layer 1, both directions)
//   GEMM2 (row-scaled)  -> agg+bias        (layer 2, both directions)
// GEMM uses 128x128x16 tiles with packed fma.rn.f32x2 accumulators.
// ---------------------------------------------------------------------------

#define NA_MAX 50000
#define NB_MAX 10000
#define E_MAX  300000

// Scratch (device globals; no allocation anywhere)
__device__ float g_h1a[NA_MAX * 256];   // (x_a*sA) @ W1_bel
__device__ float g_h1b[NB_MAX * 256];   // (x_b*sB) @ W1_inc
__device__ float g_ha [NA_MAX * 256];   // relu-aggregated layer-1 A features
__device__ float g_hb [NB_MAX * 256];   // relu-aggregated layer-1 B features
__device__ float g_h2a[NA_MAX * 128];   // (h_a*sA) @ W2_bel
__device__ float g_h2b[NB_MAX * 128];   // (h_b*sB) @ W2_inc

__device__ int   g_deg_a[NA_MAX];       // out-degree over bel_src
__device__ int   g_deg_b[NB_MAX];       // out-degree over inc_src
__device__ float g_scale_a[NA_MAX];     // rsqrt(max(deg_a,1))
__device__ float g_scale_b[NB_MAX];

__device__ int g_cnt_bel[NB_MAX];       // histogram of bel_dst
__device__ int g_cnt_inc[NA_MAX];       // histogram of inc_dst
__device__ int g_off_bel[NB_MAX + 1];
__device__ int g_off_inc[NA_MAX + 1];
__device__ int g_cur_bel[NB_MAX];
__device__ int g_cur_inc[NA_MAX];
__device__ int g_srt_bel[E_MAX];        // bel src ids sorted by dst
__device__ int g_srt_inc[E_MAX];        // inc src ids sorted by dst
__device__ int g_partials[128];

// ------------------------------ small kernels ------------------------------

__global__ void count_kernel(const int* __restrict__ idx, int* __restrict__ cnt, int n) {
    int i = blockIdx.x * blockDim.x + threadIdx.x;
    if (i < n) atomicAdd(&cnt[idx[i]], 1);
}

__global__ void scale_kernel(const int* __restrict__ deg, float* __restrict__ sc, int n) {
    int i = blockIdx.x * blockDim.x + threadIdx.x;
    if (i < n) {
        int d = deg[i];
        sc[i] = rsqrtf((float)(d > 0 ? d : 1));
    }
}

// Exclusive-scan stage 1: per-block Hillis-Steele, write block totals.
__global__ void scan_block(const int* __restrict__ cnt, int* __restrict__ off,
                           int* __restrict__ partials, int n) {
    __shared__ int s[1024];
    int i = blockIdx.x * 1024 + threadIdx.x;
    int v = (i < n) ? cnt[i] : 0;
    s[threadIdx.x] = v;
    __syncthreads();
#pragma unroll
    for (int d = 1; d < 1024; d <<= 1) {
        int t = (threadIdx.x >= d) ? s[threadIdx.x - d] : 0;
        __syncthreads();
        s[threadIdx.x] += t;
        __syncthreads();
    }
    if (i < n) off[i] = s[threadIdx.x] - v;           // exclusive within block
    if (threadIdx.x == 1023) partials[blockIdx.x] = s[1023];
}

__global__ void scan_partials(int* partials, int nb) {
    if (threadIdx.x == 0 && blockIdx.x == 0) {
        int acc = 0;
        for (int b = 0; b < nb; b++) { int t = partials[b]; partials[b] = acc; acc += t; }
    }
}

__global__ void scan_add(int* __restrict__ off, const int* __restrict__ partials,
                         int n, int total) {
    int i = blockIdx.x * blockDim.x + threadIdx.x;
    if (i < n) off[i] += partials[i >> 10];
    if (i == 0) off[n] = total;
}

__global__ void fill_csr(const int* __restrict__ src, const int* __restrict__ dst, int n,
                         int* __restrict__ cursor, int* __restrict__ srt) {
    int e = blockIdx.x * blockDim.x + threadIdx.x;
    if (e < n) {
        int p = atomicAdd(&cursor[dst[e]], 1);
        srt[p] = src[e];
    }
}

// ------------------------------ GEMM (f32x2) -------------------------------
// C[M,N] = diag(scale) * A[M,K] @ W[K,N].  N % 128 == 0, K % 16 == 0.

__device__ __forceinline__ unsigned long long pack2(float x, float y) {
    unsigned long long r;
    asm("mov.b64 %0, {%1, %2};" : "=l"(r) : "f"(x), "f"(y));
    return r;
}
__device__ __forceinline__ void fma2(unsigned long long& c, unsigned long long a,
                                     unsigned long long b) {
    asm("fma.rn.f32x2 %0, %1, %2, %0;" : "+l"(c) : "l"(a), "l"(b));
}
__device__ __forceinline__ float2 unpack2(unsigned long long v) {
    float2 r;
    asm("mov.b64 {%0, %1}, %2;" : "=f"(r.x), "=f"(r.y) : "l"(v));
    return r;
}

__global__ __launch_bounds__(256)
void gemm_scaled(const float* __restrict__ A, const float* __restrict__ scale,
                 const float* __restrict__ W, float* __restrict__ C,
                 int M, int N, int K) {
    constexpr int BM = 128, BN = 128, BK = 16;
    __shared__ float As[BM][BK + 4];   // row stride 20 floats
    __shared__ float Bs[BK][BN];

    int tid = threadIdx.x;
    int tx = tid & 15, ty = tid >> 4;
    int m0 = blockIdx.y * BM;
    int n0 = blockIdx.x * BN;

    unsigned long long c2[8][4];
#pragma unroll
    for (int i = 0; i < 8; i++)
#pragma unroll
        for (int j = 0; j < 4; j++) c2[i][j] = 0ull;

    for (int k0 = 0; k0 < K; k0 += BK) {
        // load A tile (row-scaled): 512 float4, 2 per thread
#pragma unroll
        for (int i = 0; i < 2; i++) {
            int f = tid + i * 256;
            int m = f >> 2;
            int k4 = (f & 3) * 4;
            int gm = m0 + m;
            float4 v = make_float4(0.f, 0.f, 0.f, 0.f);
            float s = 0.f;
            if (gm < M) {
                v = *reinterpret_cast<const float4*>(A + (size_t)gm * K + k0 + k4);
                s = scale[gm];
            }
            As[m][k4 + 0] = v.x * s;
            As[m][k4 + 1] = v.y * s;
            As[m][k4 + 2] = v.z * s;
            As[m][k4 + 3] = v.w * s;
        }
        // load B tile: 512 float4, 2 per thread
#pragma unroll
        for (int i = 0; i < 2; i++) {
            int f = tid + i * 256;
            int kr = f >> 5;
            int c4 = (f & 31) * 4;
            float4 v = *reinterpret_cast<const float4*>(W + (size_t)(k0 + kr) * N + n0 + c4);
            *reinterpret_cast<float4*>(&Bs[kr][c4]) = v;
        }
        __syncthreads();

#pragma unroll
        for (int k = 0; k < BK; k++) {
            float a[8];
#pragma unroll
            for (int i = 0; i < 4; i++) {
                a[i]     = As[ty * 4 + i][k];
                a[4 + i] = As[64 + ty * 4 + i][k];
            }
            float4 b0 = *reinterpret_cast<const float4*>(&Bs[k][tx * 4]);
            float4 b1 = *reinterpret_cast<const float4*>(&Bs[k][64 + tx * 4]);
            unsigned long long bp[4];
            bp[0] = pack2(b0.x, b0.y);
            bp[1] = pack2(b0.z, b0.w);
            bp[2] = pack2(b1.x, b1.y);
            bp[3] = pack2(b1.z, b1.w);
#pragma unroll
            for (int i = 0; i < 8; i++) {
                unsigned long long a2 = pack2(a[i], a[i]);
                fma2(c2[i][0], a2, bp[0]);
                fma2(c2[i][1], a2, bp[1]);
                fma2(c2[i][2], a2, bp[2]);
                fma2(c2[i][3], a2, bp[3]);
            }
        }
        __syncthreads();
    }

#pragma unroll
    for (int i = 0; i < 8; i++) {
        int gm = m0 + ((i < 4) ? (ty * 4 + i) : (64 + ty * 4 + i - 4));
        if (gm < M) {
            float2 p0 = unpack2(c2[i][0]), p1 = unpack2(c2[i][1]);
            float2 p2 = unpack2(c2[i][2]), p3 = unpack2(c2[i][3]);
            float4 v0 = make_float4(p0.x, p0.y, p1.x, p1.y);
            float4 v1 = make_float4(p2.x, p2.y, p3.x, p3.y);
            *reinterpret_cast<float4*>(C + (size_t)gm * N + n0 + tx * 4) = v0;
            *reinterpret_cast<float4*>(C + (size_t)gm * N + n0 + 64 + tx * 4) = v1;
        }
    }
}

// --------------------------- CSR aggregation -------------------------------
// out[v,:] = act( (sum_{e in csr(v)} H[srt[e],:]) * rsqrt(max(deg,1)) + bias )
// One warp per destination node; float4 lanes.

__device__ __forceinline__ void acc4(float4& a, const float4& b) {
    a.x += b.x; a.y += b.y; a.z += b.z; a.w += b.w;
}

template <int F, bool RELU>
__global__ __launch_bounds__(256)
void agg_kernel(const float* __restrict__ H, const int* __restrict__ off,
                const int* __restrict__ srt, const float* __restrict__ bias,
                float* __restrict__ out, int n) {
    int warp = (blockIdx.x * blockDim.x + threadIdx.x) >> 5;
    int lane = threadIdx.x & 31;
    if (warp >= n) return;

    int s0 = off[warp], s1 = off[warp + 1];
    float4 acc0 = make_float4(0.f, 0.f, 0.f, 0.f);
    float4 acc1 = make_float4(0.f, 0.f, 0.f, 0.f);

    int e = s0;
    for (; e + 2 <= s1; e += 2) {
        int sA = __ldg(&srt[e]);
        int sB = __ldg(&srt[e + 1]);
        const float4* rA = reinterpret_cast<const float4*>(H + (size_t)sA * F);
        const float4* rB = reinterpret_cast<const float4*>(H + (size_t)sB * F);
        float4 vA0 = __ldg(rA + lane);
        float4 vB0 = __ldg(rB + lane);
        if (F == 256) {
            float4 vA1 = __ldg(rA + 32 + lane);
            float4 vB1 = __ldg(rB + 32 + lane);
            acc4(acc1, vA1); acc4(acc1, vB1);
        }
        acc4(acc0, vA0); acc4(acc0, vB0);
    }
    if (e < s1) {
        int sA = __ldg(&srt[e]);
        const float4* rA = reinterpret_cast<const float4*>(H + (size_t)sA * F);
        acc4(acc0, __ldg(rA + lane));
        if (F == 256) acc4(acc1, __ldg(rA + 32 + lane));
    }

    int deg = s1 - s0;
    float sc = rsqrtf((float)(deg > 0 ? deg : 1));
    const float4* bv = reinterpret_cast<const float4*>(bias);
    float4 b0 = __ldg(bv + lane);
    float4 r0;
    r0.x = acc0.x * sc + b0.x;
    r0.y = acc0.y * sc + b0.y;
    r0.z = acc0.z * sc + b0.z;
    r0.w = acc0.w * sc + b0.w;
    if (RELU) {
        r0.x = fmaxf(r0.x, 0.f); r0.y = fmaxf(r0.y, 0.f);
        r0.z = fmaxf(r0.z, 0.f); r0.w = fmaxf(r0.w, 0.f);
    }
    float4* ov = reinterpret_cast<float4*>(out + (size_t)warp * F);
    ov[lane] = r0;

    if (F == 256) {
        float4 b1 = __ldg(bv + 32 + lane);
        float4 r1;
        r1.x = acc1.x * sc + b1.x;
        r1.y = acc1.y * sc + b1.y;
        r1.z = acc1.z * sc + b1.z;
        r1.w = acc1.w * sc + b1.w;
        if (RELU) {
            r1.x = fmaxf(r1.x, 0.f); r1.y = fmaxf(r1.y, 0.f);
            r1.z = fmaxf(r1.z, 0.f); r1.w = fmaxf(r1.w, 0.f);
        }
        ov[32 + lane] = r1;
    }
}

// --------------------------------- launch ----------------------------------

extern "C" void kernel_launch(void* const* d_in, const int* in_sizes, int n_in,
                              void* d_out, int out_size) {
    const float* x_a    = (const float*)d_in[0];
    const float* x_b    = (const float*)d_in[1];
    const float* W1_bel = (const float*)d_in[2];
    const float* b1_bel = (const float*)d_in[3];
    const float* W1_inc = (const float*)d_in[4];
    const float* b1_inc = (const float*)d_in[5];
    const float* W2_bel = (const float*)d_in[6];
    const float* b2_bel = (const float*)d_in[7];
    const float* W2_inc = (const float*)d_in[8];
    const float* b2_inc = (const float*)d_in[9];
    const int* bel_src  = (const int*)d_in[10];
    const int* bel_dst  = (const int*)d_in[11];
    const int* inc_src  = (const int*)d_in[12];
    const int* inc_dst  = (const int*)d_in[13];

    const int HID     = in_sizes[3];             // 256
    const int INF     = in_sizes[2] / HID;       // 256
    const int BEL_OUT = in_sizes[7];             // 128
    const int INC_OUT = in_sizes[9];             // 128
    const int NA      = in_sizes[0] / INF;       // 50000
    const int NB      = in_sizes[1] / INF;       // 10000
    const int E       = in_sizes[10];            // 300000

    float* out_a = (float*)d_out;                      // [NA, INC_OUT]
    float* out_b = out_a + (size_t)NA * INC_OUT;       // [NB, BEL_OUT]

    // Resolve scratch symbol addresses (no allocation; safe during capture).
    float *h1a, *h1b, *ha, *hb, *h2a, *h2b, *scale_a, *scale_b;
    int *deg_a, *deg_b, *cnt_bel, *cnt_inc, *off_bel, *off_inc;
    int *cur_bel, *cur_inc, *srt_bel, *srt_inc, *partials;
    cudaGetSymbolAddress((void**)&h1a, g_h1a);
    cudaGetSymbolAddress((void**)&h1b, g_h1b);
    cudaGetSymbolAddress((void**)&ha,  g_ha);
    cudaGetSymbolAddress((void**)&hb,  g_hb);
    cudaGetSymbolAddress((void**)&h2a, g_h2a);
    cudaGetSymbolAddress((void**)&h2b, g_h2b);
    cudaGetSymbolAddress((void**)&scale_a, g_scale_a);
    cudaGetSymbolAddress((void**)&scale_b, g_scale_b);
    cudaGetSymbolAddress((void**)&deg_a, g_deg_a);
    cudaGetSymbolAddress((void**)&deg_b, g_deg_b);
    cudaGetSymbolAddress((void**)&cnt_bel, g_cnt_bel);
    cudaGetSymbolAddress((void**)&cnt_inc, g_cnt_inc);
    cudaGetSymbolAddress((void**)&off_bel, g_off_bel);
    cudaGetSymbolAddress((void**)&off_inc, g_off_inc);
    cudaGetSymbolAddress((void**)&cur_bel, g_cur_bel);
    cudaGetSymbolAddress((void**)&cur_inc, g_cur_inc);
    cudaGetSymbolAddress((void**)&srt_bel, g_srt_bel);
    cudaGetSymbolAddress((void**)&srt_inc, g_srt_inc);
    cudaGetSymbolAddress((void**)&partials, g_partials);

    const int TB = 256;
    const int gE = (E + TB - 1) / TB;

    // ---- degrees + scales ----
    cudaMemsetAsync(deg_a,   0, (size_t)NA * 4);
    cudaMemsetAsync(deg_b,   0, (size_t)NB * 4);
    cudaMemsetAsync(cnt_bel, 0, (size_t)NB * 4);
    cudaMemsetAsync(cnt_inc, 0, (size_t)NA * 4);
    count_kernel<<<gE, TB>>>(bel_src, deg_a, E);
    count_kernel<<<gE, TB>>>(inc_src, deg_b, E);
    count_kernel<<<gE, TB>>>(bel_dst, cnt_bel, E);
    count_kernel<<<gE, TB>>>(inc_dst, cnt_inc, E);
    scale_kernel<<<(NA + TB - 1) / TB, TB>>>(deg_a, scale_a, NA);
    scale_kernel<<<(NB + TB - 1) / TB, TB>>>(deg_b, scale_b, NB);

    // ---- CSR for bel (by dst over NB) ----
    {
        int nb = (NB + 1023) / 1024;
        scan_block<<<nb, 1024>>>(cnt_bel, off_bel, partials, NB);
        scan_partials<<<1, 32>>>(partials, nb);
        scan_add<<<(NB + TB - 1) / TB, TB>>>(off_bel, partials, NB, E);
        cudaMemcpyAsync(cur_bel, off_bel, (size_t)NB * 4, cudaMemcpyDeviceToDevice);
        fill_csr<<<gE, TB>>>(bel_src, bel_dst, E, cur_bel, srt_bel);
    }
    // ---- CSR for inc (by dst over NA) ----
    {
        int nb = (NA + 1023) / 1024;
        scan_block<<<nb, 1024>>>(cnt_inc, off_inc, partials, NA);
        scan_partials<<<1, 32>>>(partials, nb);
        scan_add<<<(NA + TB - 1) / TB, TB>>>(off_inc, partials, NA, E);
        cudaMemcpyAsync(cur_inc, off_inc, (size_t)NA * 4, cudaMemcpyDeviceToDevice);
        fill_csr<<<gE, TB>>>(inc_src, inc_dst, E, cur_inc, srt_inc);
    }

    // ---- layer 1 ----
    gemm_scaled<<<dim3(HID / 128, (NA + 127) / 128), 256>>>(x_a, scale_a, W1_bel, h1a, NA, HID, INF);
    gemm_scaled<<<dim3(HID / 128, (NB + 127) / 128), 256>>>(x_b, scale_b, W1_inc, h1b, NB, HID, INF);
    agg_kernel<256, true><<<(NB + 7) / 8, 256>>>(h1a, off_bel, srt_bel, b1_bel, hb, NB);
    agg_kernel<256, true><<<(NA + 7) / 8, 256>>>(h1b, off_inc, srt_inc, b1_inc, ha, NA);

    // ---- layer 2 ----
    gemm_scaled<<<dim3(BEL_OUT / 128, (NA + 127) / 128), 256>>>(ha, scale_a, W2_bel, h2a, NA, BEL_OUT, HID);
    gemm_scaled<<<dim3(INC_OUT / 128, (NB + 127) / 128), 256>>>(hb, scale_b, W2_inc, h2b, NB, INC_OUT, HID);
    agg_kernel<128, false><<<(NB + 7) / 8, 256>>>(h2a, off_bel, srt_bel, b2_bel, out_b, NB);
    agg_kernel<128, false><<<(NA + 7) / 8, 256>>>(h2b, off_inc, srt_inc, b2_inc, out_a, NA);
}

// round 14
// speedup vs baseline: 1.0040x; 1.0040x over previous
#include <cuda_runtime.h>
#include <cstdint>

// ---------------------------------------------------------------------------
// RGCN (2-layer bipartite GraphConv, norm='both') for fixed shapes:
//   N_A=50000, N_B=10000, E=300000, IN_F=HID=256, OUT=128
// Pipeline per call (all on default stream, graph-capturable):
//   degrees (atomics) -> row scales -> CSR-by-dst (scan + cursor fill)
//   GEMM1 (row-scaled)  -> agg+bias+relu   (layer 1, both directions)
//   GEMM2 (row-scaled)  -> agg+bias        (layer 2, both directions)
// GEMM uses 128x128x16 tiles with packed fma.rn.f32x2 accumulators.
// ---------------------------------------------------------------------------

#define NA_MAX 50000
#define NB_MAX 10000
#define E_MAX  300000

// Scratch (device globals; no allocation anywhere)
__device__ float g_h1a[NA_MAX * 256];   // (x_a*sA) @ W1_bel
__device__ float g_h1b[NB_MAX * 256];   // (x_b*sB) @ W1_inc
__device__ float g_ha [NA_MAX * 256];   // relu-aggregated layer-1 A features
__device__ float g_hb [NB_MAX * 256];   // relu-aggregated layer-1 B features
__device__ float g_h2a[NA_MAX * 128];   // (h_a*sA) @ W2_bel
__device__ float g_h2b[NB_MAX * 128];   // (h_b*sB) @ W2_inc

__device__ int   g_deg_a[NA_MAX];       // out-degree over bel_src
__device__ int   g_deg_b[NB_MAX];       // out-degree over inc_src
__device__ float g_scale_a[NA_MAX];     // rsqrt(max(deg_a,1))
__device__ float g_scale_b[NB_MAX];

__device__ int g_cnt_bel[NB_MAX];       // histogram of bel_dst
__device__ int g_cnt_inc[NA_MAX];       // histogram of inc_dst
__device__ int g_off_bel[NB_MAX + 1];
__device__ int g_off_inc[NA_MAX + 1];
__device__ int g_cur_bel[NB_MAX];
__device__ int g_cur_inc[NA_MAX];
__device__ int g_srt_bel[E_MAX];        // bel src ids sorted by dst
__device__ int g_srt_inc[E_MAX];        // inc src ids sorted by dst
__device__ int g_partials[128];

// ------------------------------ small kernels ------------------------------

__global__ void count_kernel(const int* __restrict__ idx, int* __restrict__ cnt, int n) {
    int i = blockIdx.x * blockDim.x + threadIdx.x;
    if (i < n) atomicAdd(&cnt[idx[i]], 1);
}

__global__ void scale_kernel(const int* __restrict__ deg, float* __restrict__ sc, int n) {
    int i = blockIdx.x * blockDim.x + threadIdx.x;
    if (i < n) {
        int d = deg[i];
        sc[i] = rsqrtf((float)(d > 0 ? d : 1));
    }
}

// Exclusive-scan stage 1: per-block Hillis-Steele, write block totals.
__global__ void scan_block(const int* __restrict__ cnt, int* __restrict__ off,
                           int* __restrict__ partials, int n) {
    __shared__ int s[1024];
    int i = blockIdx.x * 1024 + threadIdx.x;
    int v = (i < n) ? cnt[i] : 0;
    s[threadIdx.x] = v;
    __syncthreads();
#pragma unroll
    for (int d = 1; d < 1024; d <<= 1) {
        int t = (threadIdx.x >= d) ? s[threadIdx.x - d] : 0;
        __syncthreads();
        s[threadIdx.x] += t;
        __syncthreads();
    }
    if (i < n) off[i] = s[threadIdx.x] - v;           // exclusive within block
    if (threadIdx.x == 1023) partials[blockIdx.x] = s[1023];
}

__global__ void scan_partials(int* partials, int nb) {
    if (threadIdx.x == 0 && blockIdx.x == 0) {
        int acc = 0;
        for (int b = 0; b < nb; b++) { int t = partials[b]; partials[b] = acc; acc += t; }
    }
}

__global__ void scan_add(int* __restrict__ off, const int* __restrict__ partials,
                         int n, int total) {
    int i = blockIdx.x * blockDim.x + threadIdx.x;
    if (i < n) off[i] += partials[i >> 10];
    if (i == 0) off[n] = total;
}

__global__ void fill_csr(const int* __restrict__ src, const int* __restrict__ dst, int n,
                         int* __restrict__ cursor, int* __restrict__ srt) {
    int e = blockIdx.x * blockDim.x + threadIdx.x;
    if (e < n) {
        int p = atomicAdd(&cursor[dst[e]], 1);
        srt[p] = src[e];
    }
}

// ------------------------------ GEMM (f32x2) -------------------------------
// C[M,N] = diag(scale) * A[M,K] @ W[K,N].  N % 128 == 0, K % 16 == 0.

__device__ __forceinline__ unsigned long long pack2(float x, float y) {
    unsigned long long r;
    asm("mov.b64 %0, {%1, %2};" : "=l"(r) : "f"(x), "f"(y));
    return r;
}
__device__ __forceinline__ void fma2(unsigned long long& c, unsigned long long a,
                                     unsigned long long b) {
    asm("fma.rn.f32x2 %0, %1, %2, %0;" : "+l"(c) : "l"(a), "l"(b));
}
__device__ __forceinline__ float2 unpack2(unsigned long long v) {
    float2 r;
    asm("mov.b64 {%0, %1}, %2;" : "=f"(r.x), "=f"(r.y) : "l"(v));
    return r;
}

__global__ __launch_bounds__(256)
void gemm_scaled(const float* __restrict__ A, const float* __restrict__ scale,
                 const float* __restrict__ W, float* __restrict__ C,
                 int M, int N, int K) {
    constexpr int BM = 128, BN = 128, BK = 16;
    __shared__ float As[BM][BK + 4];   // row stride 20 floats
    __shared__ float Bs[BK][BN];

    int tid = threadIdx.x;
    int tx = tid & 15, ty = tid >> 4;
    int m0 = blockIdx.y * BM;
    int n0 = blockIdx.x * BN;

    unsigned long long c2[8][4];
#pragma unroll
    for (int i = 0; i < 8; i++)
#pragma unroll
        for (int j = 0; j < 4; j++) c2[i][j] = 0ull;

    for (int k0 = 0; k0 < K; k0 += BK) {
        // load A tile (row-scaled): 512 float4, 2 per thread
#pragma unroll
        for (int i = 0; i < 2; i++) {
            int f = tid + i * 256;
            int m = f >> 2;
            int k4 = (f & 3) * 4;
            int gm = m0 + m;
            float4 v = make_float4(0.f, 0.f, 0.f, 0.f);
            float s = 0.f;
            if (gm < M) {
                v = *reinterpret_cast<const float4*>(A + (size_t)gm * K + k0 + k4);
                s = scale[gm];
            }
            As[m][k4 + 0] = v.x * s;
            As[m][k4 + 1] = v.y * s;
            As[m][k4 + 2] = v.z * s;
            As[m][k4 + 3] = v.w * s;
        }
        // load B tile: 512 float4, 2 per thread
#pragma unroll
        for (int i = 0; i < 2; i++) {
            int f = tid + i * 256;
            int kr = f >> 5;
            int c4 = (f & 31) * 4;
            float4 v = *reinterpret_cast<const float4*>(W + (size_t)(k0 + kr) * N + n0 + c4);
            *reinterpret_cast<float4*>(&Bs[kr][c4]) = v;
        }
        __syncthreads();

#pragma unroll
        for (int k = 0; k < BK; k++) {
            float a[8];
#pragma unroll
            for (int i = 0; i < 4; i++) {
                a[i]     = As[ty * 4 + i][k];
                a[4 + i] = As[64 + ty * 4 + i][k];
            }
            float4 b0 = *reinterpret_cast<const float4*>(&Bs[k][tx * 4]);
            float4 b1 = *reinterpret_cast<const float4*>(&Bs[k][64 + tx * 4]);
            unsigned long long bp[4];
            bp[0] = pack2(b0.x, b0.y);
            bp[1] = pack2(b0.z, b0.w);
            bp[2] = pack2(b1.x, b1.y);
            bp[3] = pack2(b1.z, b1.w);
#pragma unroll
            for (int i = 0; i < 8; i++) {
                unsigned long long a2 = pack2(a[i], a[i]);
                fma2(c2[i][0], a2, bp[0]);
                fma2(c2[i][1], a2, bp[1]);
                fma2(c2[i][2], a2, bp[2]);
                fma2(c2[i][3], a2, bp[3]);
            }
        }
        __syncthreads();
    }

#pragma unroll
    for (int i = 0; i < 8; i++) {
        int gm = m0 + ((i < 4) ? (ty * 4 + i) : (64 + ty * 4 + i - 4));
        if (gm < M) {
            float2 p0 = unpack2(c2[i][0]), p1 = unpack2(c2[i][1]);
            float2 p2 = unpack2(c2[i][2]), p3 = unpack2(c2[i][3]);
            float4 v0 = make_float4(p0.x, p0.y, p1.x, p1.y);
            float4 v1 = make_float4(p2.x, p2.y, p3.x, p3.y);
            *reinterpret_cast<float4*>(C + (size_t)gm * N + n0 + tx * 4) = v0;
            *reinterpret_cast<float4*>(C + (size_t)gm * N + n0 + 64 + tx * 4) = v1;
        }
    }
}

// --------------------------- CSR aggregation -------------------------------
// out[v,:] = act( (sum_{e in csr(v)} H[srt[e],:]) * rsqrt(max(deg,1)) + bias )
// One warp per destination node; float4 lanes.

__device__ __forceinline__ void acc4(float4& a, const float4& b) {
    a.x += b.x; a.y += b.y; a.z += b.z; a.w += b.w;
}

template <int F, bool RELU>
__global__ __launch_bounds__(256)
void agg_kernel(const float* __restrict__ H, const int* __restrict__ off,
                const int* __restrict__ srt, const float* __restrict__ bias,
                float* __restrict__ out, int n) {
    int warp = (blockIdx.x * blockDim.x + threadIdx.x) >> 5;
    int lane = threadIdx.x & 31;
    if (warp >= n) return;

    int s0 = off[warp], s1 = off[warp + 1];
    float4 acc0 = make_float4(0.f, 0.f, 0.f, 0.f);
    float4 acc1 = make_float4(0.f, 0.f, 0.f, 0.f);

    int e = s0;
    for (; e + 2 <= s1; e += 2) {
        int sA = __ldg(&srt[e]);
        int sB = __ldg(&srt[e + 1]);
        const float4* rA = reinterpret_cast<const float4*>(H + (size_t)sA * F);
        const float4* rB = reinterpret_cast<const float4*>(H + (size_t)sB * F);
        float4 vA0 = __ldg(rA + lane);
        float4 vB0 = __ldg(rB + lane);
        if (F == 256) {
            float4 vA1 = __ldg(rA + 32 + lane);
            float4 vB1 = __ldg(rB + 32 + lane);
            acc4(acc1, vA1); acc4(acc1, vB1);
        }
        acc4(acc0, vA0); acc4(acc0, vB0);
    }
    if (e < s1) {
        int sA = __ldg(&srt[e]);
        const float4* rA = reinterpret_cast<const float4*>(H + (size_t)sA * F);
        acc4(acc0, __ldg(rA + lane));
        if (F == 256) acc4(acc1, __ldg(rA + 32 + lane));
    }

    int deg = s1 - s0;
    float sc = rsqrtf((float)(deg > 0 ? deg : 1));
    const float4* bv = reinterpret_cast<const float4*>(bias);
    float4 b0 = __ldg(bv + lane);
    float4 r0;
    r0.x = acc0.x * sc + b0.x;
    r0.y = acc0.y * sc + b0.y;
    r0.z = acc0.z * sc + b0.z;
    r0.w = acc0.w * sc + b0.w;
    if (RELU) {
        r0.x = fmaxf(r0.x, 0.f); r0.y = fmaxf(r0.y, 0.f);
        r0.z = fmaxf(r0.z, 0.f); r0.w = fmaxf(r0.w, 0.f);
    }
    float4* ov = reinterpret_cast<float4*>(out + (size_t)warp * F);
    ov[lane] = r0;

    if (F == 256) {
        float4 b1 = __ldg(bv + 32 + lane);
        float4 r1;
        r1.x = acc1.x * sc + b1.x;
        r1.y = acc1.y * sc + b1.y;
        r1.z = acc1.z * sc + b1.z;
        r1.w = acc1.w * sc + b1.w;
        if (RELU) {
            r1.x = fmaxf(r1.x, 0.f); r1.y = fmaxf(r1.y, 0.f);
            r1.z = fmaxf(r1.z, 0.f); r1.w = fmaxf(r1.w, 0.f);
        }
        ov[32 + lane] = r1;
    }
}

// --------------------------------- launch ----------------------------------

extern "C" void kernel_launch(void* const* d_in, const int* in_sizes, int n_in,
                              void* d_out, int out_size) {
    const float* x_a    = (const float*)d_in[0];
    const float* x_b    = (const float*)d_in[1];
    const float* W1_bel = (const float*)d_in[2];
    const float* b1_bel = (const float*)d_in[3];
    const float* W1_inc = (const float*)d_in[4];
    const float* b1_inc = (const float*)d_in[5];
    const float* W2_bel = (const float*)d_in[6];
    const float* b2_bel = (const float*)d_in[7];
    const float* W2_inc = (const float*)d_in[8];
    const float* b2_inc = (const float*)d_in[9];
    const int* bel_src  = (const int*)d_in[10];
    const int* bel_dst  = (const int*)d_in[11];
    const int* inc_src  = (const int*)d_in[12];
    const int* inc_dst  = (const int*)d_in[13];

    const int HID     = in_sizes[3];             // 256
    const int INF     = in_sizes[2] / HID;       // 256
    const int BEL_OUT = in_sizes[7];             // 128
    const int INC_OUT = in_sizes[9];             // 128
    const int NA      = in_sizes[0] / INF;       // 50000
    const int NB      = in_sizes[1] / INF;       // 10000
    const int E       = in_sizes[10];            // 300000

    float* out_a = (float*)d_out;                      // [NA, INC_OUT]
    float* out_b = out_a + (size_t)NA * INC_OUT;       // [NB, BEL_OUT]

    // Resolve scratch symbol addresses (no allocation; safe during capture).
    float *h1a, *h1b, *ha, *hb, *h2a, *h2b, *scale_a, *scale_b;
    int *deg_a, *deg_b, *cnt_bel, *cnt_inc, *off_bel, *off_inc;
    int *cur_bel, *cur_inc, *srt_bel, *srt_inc, *partials;
    cudaGetSymbolAddress((void**)&h1a, g_h1a);
    cudaGetSymbolAddress((void**)&h1b, g_h1b);
    cudaGetSymbolAddress((void**)&ha,  g_ha);
    cudaGetSymbolAddress((void**)&hb,  g_hb);
    cudaGetSymbolAddress((void**)&h2a, g_h2a);
    cudaGetSymbolAddress((void**)&h2b, g_h2b);
    cudaGetSymbolAddress((void**)&scale_a, g_scale_a);
    cudaGetSymbolAddress((void**)&scale_b, g_scale_b);
    cudaGetSymbolAddress((void**)&deg_a, g_deg_a);
    cudaGetSymbolAddress((void**)&deg_b, g_deg_b);
    cudaGetSymbolAddress((void**)&cnt_bel, g_cnt_bel);
    cudaGetSymbolAddress((void**)&cnt_inc, g_cnt_inc);
    cudaGetSymbolAddress((void**)&off_bel, g_off_bel);
    cudaGetSymbolAddress((void**)&off_inc, g_off_inc);
    cudaGetSymbolAddress((void**)&cur_bel, g_cur_bel);
    cudaGetSymbolAddress((void**)&cur_inc, g_cur_inc);
    cudaGetSymbolAddress((void**)&srt_bel, g_srt_bel);
    cudaGetSymbolAddress((void**)&srt_inc, g_srt_inc);
    cudaGetSymbolAddress((void**)&partials, g_partials);

    const int TB = 256;
    const int gE = (E + TB - 1) / TB;

    // ---- degrees + scales ----
    cudaMemsetAsync(deg_a,   0, (size_t)NA * 4);
    cudaMemsetAsync(deg_b,   0, (size_t)NB * 4);
    cudaMemsetAsync(cnt_bel, 0, (size_t)NB * 4);
    cudaMemsetAsync(cnt_inc, 0, (size_t)NA * 4);
    count_kernel<<<gE, TB>>>(bel_src, deg_a, E);
    count_kernel<<<gE, TB>>>(inc_src, deg_b, E);
    count_kernel<<<gE, TB>>>(bel_dst, cnt_bel, E);
    count_kernel<<<gE, TB>>>(inc_dst, cnt_inc, E);
    scale_kernel<<<(NA + TB - 1) / TB, TB>>>(deg_a, scale_a, NA);
    scale_kernel<<<(NB + TB - 1) / TB, TB>>>(deg_b, scale_b, NB);

    // ---- CSR for bel (by dst over NB) ----
    {
        int nb = (NB + 1023) / 1024;
        scan_block<<<nb, 1024>>>(cnt_bel, off_bel, partials, NB);
        scan_partials<<<1, 32>>>(partials, nb);
        scan_add<<<(NB + TB - 1) / TB, TB>>>(off_bel, partials, NB, E);
        cudaMemcpyAsync(cur_bel, off_bel, (size_t)NB * 4, cudaMemcpyDeviceToDevice);
        fill_csr<<<gE, TB>>>(bel_src, bel_dst, E, cur_bel, srt_bel);
    }
    // ---- CSR for inc (by dst over NA) ----
    {
        int nb = (NA + 1023) / 1024;
        scan_block<<<nb, 1024>>>(cnt_inc, off_inc, partials, NA);
        scan_partials<<<1, 32>>>(partials, nb);
        scan_add<<<(NA + TB - 1) / TB, TB>>>(off_inc, partials, NA, E);
        cudaMemcpyAsync(cur_inc, off_inc, (size_t)NA * 4, cudaMemcpyDeviceToDevice);
        fill_csr<<<gE, TB>>>(inc_src, inc_dst, E, cur_inc, srt_inc);
    }

    // ---- layer 1 ----
    gemm_scaled<<<dim3(HID / 128, (NA + 127) / 128), 256>>>(x_a, scale_a, W1_bel, h1a, NA, HID, INF);
    gemm_scaled<<<dim3(HID / 128, (NB + 127) / 128), 256>>>(x_b, scale_b, W1_inc, h1b, NB, HID, INF);
    agg_kernel<256, true><<<(NB + 7) / 8, 256>>>(h1a, off_bel, srt_bel, b1_bel, hb, NB);
    agg_kernel<256, true><<<(NA + 7) / 8, 256>>>(h1b, off_inc, srt_inc, b1_inc, ha, NA);

    // ---- layer 2 ----
    gemm_scaled<<<dim3(BEL_OUT / 128, (NA + 127) / 128), 256>>>(ha, scale_a, W2_bel, h2a, NA, BEL_OUT, HID);
    gemm_scaled<<<dim3(INC_OUT / 128, (NB + 127) / 128), 256>>>(hb, scale_b, W2_inc, h2b, NB, INC_OUT, HID);
    agg_kernel<128, false><<<(NB + 7) / 8, 256>>>(h2a, off_bel, srt_bel, b2_bel, out_b, NB);
    agg_kernel<128, false><<<(NA + 7) / 8, 256>>>(h2b, off_inc, srt_inc, b2_inc, out_a, NA);
}

// round 15
// speedup vs baseline: 1.0043x; 1.0002x over previous
#include <cuda_runtime.h>
#include <cstdint>

// ---------------------------------------------------------------------------
// RGCN (2-layer bipartite GraphConv, norm='both') for fixed shapes:
//   N_A=50000, N_B=10000, E=300000, IN_F=HID=256, OUT=128
// Pipeline per call (all on default stream, graph-capturable):
//   degrees (atomics) -> row scales -> CSR-by-dst (scan + cursor fill)
//   GEMM1 (row-scaled)  -> agg+bias+relu   (layer 1, both directions)
//   GEMM2 (row-scaled)  -> agg+bias        (layer 2, both directions)
// GEMM uses 128x128x16 tiles with packed fma.rn.f32x2 accumulators.
// ---------------------------------------------------------------------------

#define NA_MAX 50000
#define NB_MAX 10000
#define E_MAX  300000

// Scratch (device globals; no allocation anywhere)
__device__ float g_h1a[NA_MAX * 256];   // (x_a*sA) @ W1_bel
__device__ float g_h1b[NB_MAX * 256];   // (x_b*sB) @ W1_inc
__device__ float g_ha [NA_MAX * 256];   // relu-aggregated layer-1 A features
__device__ float g_hb [NB_MAX * 256];   // relu-aggregated layer-1 B features
__device__ float g_h2a[NA_MAX * 128];   // (h_a*sA) @ W2_bel
__device__ float g_h2b[NB_MAX * 128];   // (h_b*sB) @ W2_inc

__device__ int   g_deg_a[NA_MAX];       // out-degree over bel_src
__device__ int   g_deg_b[NB_MAX];       // out-degree over inc_src
__device__ float g_scale_a[NA_MAX];     // rsqrt(max(deg_a,1))
__device__ float g_scale_b[NB_MAX];

__device__ int g_cnt_bel[NB_MAX];       // histogram of bel_dst
__device__ int g_cnt_inc[NA_MAX];       // histogram of inc_dst
__device__ int g_off_bel[NB_MAX + 1];
__device__ int g_off_inc[NA_MAX + 1];
__device__ int g_cur_bel[NB_MAX];
__device__ int g_cur_inc[NA_MAX];
__device__ int g_srt_bel[E_MAX];        // bel src ids sorted by dst
__device__ int g_srt_inc[E_MAX];        // inc src ids sorted by dst
__device__ int g_partials[128];

// ------------------------------ small kernels ------------------------------

__global__ void count_kernel(const int* __restrict__ idx, int* __restrict__ cnt, int n) {
    int i = blockIdx.x * blockDim.x + threadIdx.x;
    if (i < n) atomicAdd(&cnt[idx[i]], 1);
}

__global__ void scale_kernel(const int* __restrict__ deg, float* __restrict__ sc, int n) {
    int i = blockIdx.x * blockDim.x + threadIdx.x;
    if (i < n) {
        int d = deg[i];
        sc[i] = rsqrtf((float)(d > 0 ? d : 1));
    }
}

// Exclusive-scan stage 1: per-block Hillis-Steele, write block totals.
__global__ void scan_block(const int* __restrict__ cnt, int* __restrict__ off,
                           int* __restrict__ partials, int n) {
    __shared__ int s[1024];
    int i = blockIdx.x * 1024 + threadIdx.x;
    int v = (i < n) ? cnt[i] : 0;
    s[threadIdx.x] = v;
    __syncthreads();
#pragma unroll
    for (int d = 1; d < 1024; d <<= 1) {
        int t = (threadIdx.x >= d) ? s[threadIdx.x - d] : 0;
        __syncthreads();
        s[threadIdx.x] += t;
        __syncthreads();
    }
    if (i < n) off[i] = s[threadIdx.x] - v;           // exclusive within block
    if (threadIdx.x == 1023) partials[blockIdx.x] = s[1023];
}

__global__ void scan_partials(int* partials, int nb) {
    if (threadIdx.x == 0 && blockIdx.x == 0) {
        int acc = 0;
        for (int b = 0; b < nb; b++) { int t = partials[b]; partials[b] = acc; acc += t; }
    }
}

__global__ void scan_add(int* __restrict__ off, const int* __restrict__ partials,
                         int n, int total) {
    int i = blockIdx.x * blockDim.x + threadIdx.x;
    if (i < n) off[i] += partials[i >> 10];
    if (i == 0) off[n] = total;
}

__global__ void fill_csr(const int* __restrict__ src, const int* __restrict__ dst, int n,
                         int* __restrict__ cursor, int* __restrict__ srt) {
    int e = blockIdx.x * blockDim.x + threadIdx.x;
    if (e < n) {
        int p = atomicAdd(&cursor[dst[e]], 1);
        srt[p] = src[e];
    }
}

// ------------------------------ GEMM (f32x2) -------------------------------
// C[M,N] = diag(scale) * A[M,K] @ W[K,N].  N % 128 == 0, K % 16 == 0.

__device__ __forceinline__ unsigned long long pack2(float x, float y) {
    unsigned long long r;
    asm("mov.b64 %0, {%1, %2};" : "=l"(r) : "f"(x), "f"(y));
    return r;
}
__device__ __forceinline__ void fma2(unsigned long long& c, unsigned long long a,
                                     unsigned long long b) {
    asm("fma.rn.f32x2 %0, %1, %2, %0;" : "+l"(c) : "l"(a), "l"(b));
}
__device__ __forceinline__ float2 unpack2(unsigned long long v) {
    float2 r;
    asm("mov.b64 {%0, %1}, %2;" : "=f"(r.x), "=f"(r.y) : "l"(v));
    return r;
}

__global__ __launch_bounds__(256)
void gemm_scaled(const float* __restrict__ A, const float* __restrict__ scale,
                 const float* __restrict__ W, float* __restrict__ C,
                 int M, int N, int K) {
    constexpr int BM = 128, BN = 128, BK = 16;
    __shared__ float As[BM][BK + 4];   // row stride 20 floats
    __shared__ float Bs[BK][BN];

    int tid = threadIdx.x;
    int tx = tid & 15, ty = tid >> 4;
    int m0 = blockIdx.y * BM;
    int n0 = blockIdx.x * BN;

    unsigned long long c2[8][4];
#pragma unroll
    for (int i = 0; i < 8; i++)
#pragma unroll
        for (int j = 0; j < 4; j++) c2[i][j] = 0ull;

    for (int k0 = 0; k0 < K; k0 += BK) {
        // load A tile (row-scaled): 512 float4, 2 per thread
#pragma unroll
        for (int i = 0; i < 2; i++) {
            int f = tid + i * 256;
            int m = f >> 2;
            int k4 = (f & 3) * 4;
            int gm = m0 + m;
            float4 v = make_float4(0.f, 0.f, 0.f, 0.f);
            float s = 0.f;
            if (gm < M) {
                v = *reinterpret_cast<const float4*>(A + (size_t)gm * K + k0 + k4);
                s = scale[gm];
            }
            As[m][k4 + 0] = v.x * s;
            As[m][k4 + 1] = v.y * s;
            As[m][k4 + 2] = v.z * s;
            As[m][k4 + 3] = v.w * s;
        }
        // load B tile: 512 float4, 2 per thread
#pragma unroll
        for (int i = 0; i < 2; i++) {
            int f = tid + i * 256;
            int kr = f >> 5;
            int c4 = (f & 31) * 4;
            float4 v = *reinterpret_cast<const float4*>(W + (size_t)(k0 + kr) * N + n0 + c4);
            *reinterpret_cast<float4*>(&Bs[kr][c4]) = v;
        }
        __syncthreads();

#pragma unroll
        for (int k = 0; k < BK; k++) {
            float a[8];
#pragma unroll
            for (int i = 0; i < 4; i++) {
                a[i]     = As[ty * 4 + i][k];
                a[4 + i] = As[64 + ty * 4 + i][k];
            }
            float4 b0 = *reinterpret_cast<const float4*>(&Bs[k][tx * 4]);
            float4 b1 = *reinterpret_cast<const float4*>(&Bs[k][64 + tx * 4]);
            unsigned long long bp[4];
            bp[0] = pack2(b0.x, b0.y);
            bp[1] = pack2(b0.z, b0.w);
            bp[2] = pack2(b1.x, b1.y);
            bp[3] = pack2(b1.z, b1.w);
#pragma unroll
            for (int i = 0; i < 8; i++) {
                unsigned long long a2 = pack2(a[i], a[i]);
                fma2(c2[i][0], a2, bp[0]);
                fma2(c2[i][1], a2, bp[1]);
                fma2(c2[i][2], a2, bp[2]);
                fma2(c2[i][3], a2, bp[3]);
            }
        }
        __syncthreads();
    }

#pragma unroll
    for (int i = 0; i < 8; i++) {
        int gm = m0 + ((i < 4) ? (ty * 4 + i) : (64 + ty * 4 + i - 4));
        if (gm < M) {
            float2 p0 = unpack2(c2[i][0]), p1 = unpack2(c2[i][1]);
            float2 p2 = unpack2(c2[i][2]), p3 = unpack2(c2[i][3]);
            float4 v0 = make_float4(p0.x, p0.y, p1.x, p1.y);
            float4 v1 = make_float4(p2.x, p2.y, p3.x, p3.y);
            *reinterpret_cast<float4*>(C + (size_t)gm * N + n0 + tx * 4) = v0;
            *reinterpret_cast<float4*>(C + (size_t)gm * N + n0 + 64 + tx * 4) = v1;
        }
    }
}

// --------------------------- CSR aggregation -------------------------------
// out[v,:] = act( (sum_{e in csr(v)} H[srt[e],:]) * rsqrt(max(deg,1)) + bias )
// One warp per destination node; float4 lanes.

__device__ __forceinline__ void acc4(float4& a, const float4& b) {
    a.x += b.x; a.y += b.y; a.z += b.z; a.w += b.w;
}

template <int F, bool RELU>
__global__ __launch_bounds__(256)
void agg_kernel(const float* __restrict__ H, const int* __restrict__ off,
                const int* __restrict__ srt, const float* __restrict__ bias,
                float* __restrict__ out, int n) {
    int warp = (blockIdx.x * blockDim.x + threadIdx.x) >> 5;
    int lane = threadIdx.x & 31;
    if (warp >= n) return;

    int s0 = off[warp], s1 = off[warp + 1];
    float4 acc0 = make_float4(0.f, 0.f, 0.f, 0.f);
    float4 acc1 = make_float4(0.f, 0.f, 0.f, 0.f);

    int e = s0;
    for (; e + 2 <= s1; e += 2) {
        int sA = __ldg(&srt[e]);
        int sB = __ldg(&srt[e + 1]);
        const float4* rA = reinterpret_cast<const float4*>(H + (size_t)sA * F);
        const float4* rB = reinterpret_cast<const float4*>(H + (size_t)sB * F);
        float4 vA0 = __ldg(rA + lane);
        float4 vB0 = __ldg(rB + lane);
        if (F == 256) {
            float4 vA1 = __ldg(rA + 32 + lane);
            float4 vB1 = __ldg(rB + 32 + lane);
            acc4(acc1, vA1); acc4(acc1, vB1);
        }
        acc4(acc0, vA0); acc4(acc0, vB0);
    }
    if (e < s1) {
        int sA = __ldg(&srt[e]);
        const float4* rA = reinterpret_cast<const float4*>(H + (size_t)sA * F);
        acc4(acc0, __ldg(rA + lane));
        if (F == 256) acc4(acc1, __ldg(rA + 32 + lane));
    }

    int deg = s1 - s0;
    float sc = rsqrtf((float)(deg > 0 ? deg : 1));
    const float4* bv = reinterpret_cast<const float4*>(bias);
    float4 b0 = __ldg(bv + lane);
    float4 r0;
    r0.x = acc0.x * sc + b0.x;
    r0.y = acc0.y * sc + b0.y;
    r0.z = acc0.z * sc + b0.z;
    r0.w = acc0.w * sc + b0.w;
    if (RELU) {
        r0.x = fmaxf(r0.x, 0.f); r0.y = fmaxf(r0.y, 0.f);
        r0.z = fmaxf(r0.z, 0.f); r0.w = fmaxf(r0.w, 0.f);
    }
    float4* ov = reinterpret_cast<float4*>(out + (size_t)warp * F);
    ov[lane] = r0;

    if (F == 256) {
        float4 b1 = __ldg(bv + 32 + lane);
        float4 r1;
        r1.x = acc1.x * sc + b1.x;
        r1.y = acc1.y * sc + b1.y;
        r1.z = acc1.z * sc + b1.z;
        r1.w = acc1.w * sc + b1.w;
        if (RELU) {
            r1.x = fmaxf(r1.x, 0.f); r1.y = fmaxf(r1.y, 0.f);
            r1.z = fmaxf(r1.z, 0.f); r1.w = fmaxf(r1.w, 0.f);
        }
        ov[32 + lane] = r1;
    }
}

// --------------------------------- launch ----------------------------------

extern "C" void kernel_launch(void* const* d_in, const int* in_sizes, int n_in,
                              void* d_out, int out_size) {
    const float* x_a    = (const float*)d_in[0];
    const float* x_b    = (const float*)d_in[1];
    const float* W1_bel = (const float*)d_in[2];
    const float* b1_bel = (const float*)d_in[3];
    const float* W1_inc = (const float*)d_in[4];
    const float* b1_inc = (const float*)d_in[5];
    const float* W2_bel = (const float*)d_in[6];
    const float* b2_bel = (const float*)d_in[7];
    const float* W2_inc = (const float*)d_in[8];
    const float* b2_inc = (const float*)d_in[9];
    const int* bel_src  = (const int*)d_in[10];
    const int* bel_dst  = (const int*)d_in[11];
    const int* inc_src  = (const int*)d_in[12];
    const int* inc_dst  = (const int*)d_in[13];

    const int HID     = in_sizes[3];             // 256
    const int INF     = in_sizes[2] / HID;       // 256
    const int BEL_OUT = in_sizes[7];             // 128
    const int INC_OUT = in_sizes[9];             // 128
    const int NA      = in_sizes[0] / INF;       // 50000
    const int NB      = in_sizes[1] / INF;       // 10000
    const int E       = in_sizes[10];            // 300000

    float* out_a = (float*)d_out;                      // [NA, INC_OUT]
    float* out_b = out_a + (size_t)NA * INC_OUT;       // [NB, BEL_OUT]

    // Resolve scratch symbol addresses (no allocation; safe during capture).
    float *h1a, *h1b, *ha, *hb, *h2a, *h2b, *scale_a, *scale_b;
    int *deg_a, *deg_b, *cnt_bel, *cnt_inc, *off_bel, *off_inc;
    int *cur_bel, *cur_inc, *srt_bel, *srt_inc, *partials;
    cudaGetSymbolAddress((void**)&h1a, g_h1a);
    cudaGetSymbolAddress((void**)&h1b, g_h1b);
    cudaGetSymbolAddress((void**)&ha,  g_ha);
    cudaGetSymbolAddress((void**)&hb,  g_hb);
    cudaGetSymbolAddress((void**)&h2a, g_h2a);
    cudaGetSymbolAddress((void**)&h2b, g_h2b);
    cudaGetSymbolAddress((void**)&scale_a, g_scale_a);
    cudaGetSymbolAddress((void**)&scale_b, g_scale_b);
    cudaGetSymbolAddress((void**)&deg_a, g_deg_a);
    cudaGetSymbolAddress((void**)&deg_b, g_deg_b);
    cudaGetSymbolAddress((void**)&cnt_bel, g_cnt_bel);
    cudaGetSymbolAddress((void**)&cnt_inc, g_cnt_inc);
    cudaGetSymbolAddress((void**)&off_bel, g_off_bel);
    cudaGetSymbolAddress((void**)&off_inc, g_off_inc);
    cudaGetSymbolAddress((void**)&cur_bel, g_cur_bel);
    cudaGetSymbolAddress((void**)&cur_inc, g_cur_inc);
    cudaGetSymbolAddress((void**)&srt_bel, g_srt_bel);
    cudaGetSymbolAddress((void**)&srt_inc, g_srt_inc);
    cudaGetSymbolAddress((void**)&partials, g_partials);

    const int TB = 256;
    const int gE = (E + TB - 1) / TB;

    // ---- degrees + scales ----
    cudaMemsetAsync(deg_a,   0, (size_t)NA * 4);
    cudaMemsetAsync(deg_b,   0, (size_t)NB * 4);
    cudaMemsetAsync(cnt_bel, 0, (size_t)NB * 4);
    cudaMemsetAsync(cnt_inc, 0, (size_t)NA * 4);
    count_kernel<<<gE, TB>>>(bel_src, deg_a, E);
    count_kernel<<<gE, TB>>>(inc_src, deg_b, E);
    count_kernel<<<gE, TB>>>(bel_dst, cnt_bel, E);
    count_kernel<<<gE, TB>>>(inc_dst, cnt_inc, E);
    scale_kernel<<<(NA + TB - 1) / TB, TB>>>(deg_a, scale_a, NA);
    scale_kernel<<<(NB + TB - 1) / TB, TB>>>(deg_b, scale_b, NB);

    // ---- CSR for bel (by dst over NB) ----
    {
        int nb = (NB + 1023) / 1024;
        scan_block<<<nb, 1024>>>(cnt_bel, off_bel, partials, NB);
        scan_partials<<<1, 32>>>(partials, nb);
        scan_add<<<(NB + TB - 1) / TB, TB>>>(off_bel, partials, NB, E);
        cudaMemcpyAsync(cur_bel, off_bel, (size_t)NB * 4, cudaMemcpyDeviceToDevice);
        fill_csr<<<gE, TB>>>(bel_src, bel_dst, E, cur_bel, srt_bel);
    }
    // ---- CSR for inc (by dst over NA) ----
    {
        int nb = (NA + 1023) / 1024;
        scan_block<<<nb, 1024>>>(cnt_inc, off_inc, partials, NA);
        scan_partials<<<1, 32>>>(partials, nb);
        scan_add<<<(NA + TB - 1) / TB, TB>>>(off_inc, partials, NA, E);
        cudaMemcpyAsync(cur_inc, off_inc, (size_t)NA * 4, cudaMemcpyDeviceToDevice);
        fill_csr<<<gE, TB>>>(inc_src, inc_dst, E, cur_inc, srt_inc);
    }

    // ---- layer 1 ----
    gemm_scaled<<<dim3(HID / 128, (NA + 127) / 128), 256>>>(x_a, scale_a, W1_bel, h1a, NA, HID, INF);
    gemm_scaled<<<dim3(HID / 128, (NB + 127) / 128), 256>>>(x_b, scale_b, W1_inc, h1b, NB, HID, INF);
    agg_kernel<256, true><<<(NB + 7) / 8, 256>>>(h1a, off_bel, srt_bel, b1_bel, hb, NB);
    agg_kernel<256, true><<<(NA + 7) / 8, 256>>>(h1b, off_inc, srt_inc, b1_inc, ha, NA);

    // ---- layer 2 ----
    gemm_scaled<<<dim3(BEL_OUT / 128, (NA + 127) / 128), 256>>>(ha, scale_a, W2_bel, h2a, NA, BEL_OUT, HID);
    gemm_scaled<<<dim3(INC_OUT / 128, (NB + 127) / 128), 256>>>(hb, scale_b, W2_inc, h2b, NB, INC_OUT, HID);
    agg_kernel<128, false><<<(NB + 7) / 8, 256>>>(h2a, off_bel, srt_bel, b2_bel, out_b, NB);
    agg_kernel<128, false><<<(NA + 7) / 8, 256>>>(h2b, off_inc, srt_inc, b2_inc, out_a, NA);
}

// round 16
// speedup vs baseline: 1.0048x; 1.0005x over previous
#include <cuda_runtime.h>
#include <cstdint>

// ---------------------------------------------------------------------------
// RGCN (2-layer bipartite GraphConv, norm='both') for fixed shapes:
//   N_A=50000, N_B=10000, E=300000, IN_F=HID=256, OUT=128
// Pipeline per call (all on default stream, graph-capturable):
//   degrees (atomics) -> row scales -> CSR-by-dst (scan + cursor fill)
//   GEMM1 (row-scaled)  -> agg+bias+relu   (layer 1, both directions)
//   GEMM2 (row-scaled)  -> agg+bias        (layer 2, both directions)
// GEMM uses 128x128x16 tiles with packed fma.rn.f32x2 accumulators.
// ---------------------------------------------------------------------------

#define NA_MAX 50000
#define NB_MAX 10000
#define E_MAX  300000

// Scratch (device globals; no allocation anywhere)
__device__ float g_h1a[NA_MAX * 256];   // (x_a*sA) @ W1_bel
__device__ float g_h1b[NB_MAX * 256];   // (x_b*sB) @ W1_inc
__device__ float g_ha [NA_MAX * 256];   // relu-aggregated layer-1 A features
__device__ float g_hb [NB_MAX * 256];   // relu-aggregated layer-1 B features
__device__ float g_h2a[NA_MAX * 128];   // (h_a*sA) @ W2_bel
__device__ float g_h2b[NB_MAX * 128];   // (h_b*sB) @ W2_inc

__device__ int   g_deg_a[NA_MAX];       // out-degree over bel_src
__device__ int   g_deg_b[NB_MAX];       // out-degree over inc_src
__device__ float g_scale_a[NA_MAX];     // rsqrt(max(deg_a,1))
__device__ float g_scale_b[NB_MAX];

__device__ int g_cnt_bel[NB_MAX];       // histogram of bel_dst
__device__ int g_cnt_inc[NA_MAX];       // histogram of inc_dst
__device__ int g_off_bel[NB_MAX + 1];
__device__ int g_off_inc[NA_MAX + 1];
__device__ int g_cur_bel[NB_MAX];
__device__ int g_cur_inc[NA_MAX];
__device__ int g_srt_bel[E_MAX];        // bel src ids sorted by dst
__device__ int g_srt_inc[E_MAX];        // inc src ids sorted by dst
__device__ int g_partials[128];

// ------------------------------ small kernels ------------------------------

__global__ void count_kernel(const int* __restrict__ idx, int* __restrict__ cnt, int n) {
    int i = blockIdx.x * blockDim.x + threadIdx.x;
    if (i < n) atomicAdd(&cnt[idx[i]], 1);
}

__global__ void scale_kernel(const int* __restrict__ deg, float* __restrict__ sc, int n) {
    int i = blockIdx.x * blockDim.x + threadIdx.x;
    if (i < n) {
        int d = deg[i];
        sc[i] = rsqrtf((float)(d > 0 ? d : 1));
    }
}

// Exclusive-scan stage 1: per-block Hillis-Steele, write block totals.
__global__ void scan_block(const int* __restrict__ cnt, int* __restrict__ off,
                           int* __restrict__ partials, int n) {
    __shared__ int s[1024];
    int i = blockIdx.x * 1024 + threadIdx.x;
    int v = (i < n) ? cnt[i] : 0;
    s[threadIdx.x] = v;
    __syncthreads();
#pragma unroll
    for (int d = 1; d < 1024; d <<= 1) {
        int t = (threadIdx.x >= d) ? s[threadIdx.x - d] : 0;
        __syncthreads();
        s[threadIdx.x] += t;
        __syncthreads();
    }
    if (i < n) off[i] = s[threadIdx.x] - v;           // exclusive within block
    if (threadIdx.x == 1023) partials[blockIdx.x] = s[1023];
}

__global__ void scan_partials(int* partials, int nb) {
    if (threadIdx.x == 0 && blockIdx.x == 0) {
        int acc = 0;
        for (int b = 0; b < nb; b++) { int t = partials[b]; partials[b] = acc; acc += t; }
    }
}

__global__ void scan_add(int* __restrict__ off, const int* __restrict__ partials,
                         int n, int total) {
    int i = blockIdx.x * blockDim.x + threadIdx.x;
    if (i < n) off[i] += partials[i >> 10];
    if (i == 0) off[n] = total;
}

__global__ void fill_csr(const int* __restrict__ src, const int* __restrict__ dst, int n,
                         int* __restrict__ cursor, int* __restrict__ srt) {
    int e = blockIdx.x * blockDim.x + threadIdx.x;
    if (e < n) {
        int p = atomicAdd(&cursor[dst[e]], 1);
        srt[p] = src[e];
    }
}

// ------------------------------ GEMM (f32x2) -------------------------------
// C[M,N] = diag(scale) * A[M,K] @ W[K,N].  N % 128 == 0, K % 16 == 0.

__device__ __forceinline__ unsigned long long pack2(float x, float y) {
    unsigned long long r;
    asm("mov.b64 %0, {%1, %2};" : "=l"(r) : "f"(x), "f"(y));
    return r;
}
__device__ __forceinline__ void fma2(unsigned long long& c, unsigned long long a,
                                     unsigned long long b) {
    asm("fma.rn.f32x2 %0, %1, %2, %0;" : "+l"(c) : "l"(a), "l"(b));
}
__device__ __forceinline__ float2 unpack2(unsigned long long v) {
    float2 r;
    asm("mov.b64 {%0, %1}, %2;" : "=f"(r.x), "=f"(r.y) : "l"(v));
    return r;
}

__global__ __launch_bounds__(256)
void gemm_scaled(const float* __restrict__ A, const float* __restrict__ scale,
                 const float* __restrict__ W, float* __restrict__ C,
                 int M, int N, int K) {
    constexpr int BM = 128, BN = 128, BK = 16;
    __shared__ float As[BM][BK + 4];   // row stride 20 floats
    __shared__ float Bs[BK][BN];

    int tid = threadIdx.x;
    int tx = tid & 15, ty = tid >> 4;
    int m0 = blockIdx.y * BM;
    int n0 = blockIdx.x * BN;

    unsigned long long c2[8][4];
#pragma unroll
    for (int i = 0; i < 8; i++)
#pragma unroll
        for (int j = 0; j < 4; j++) c2[i][j] = 0ull;

    for (int k0 = 0; k0 < K; k0 += BK) {
        // load A tile (row-scaled): 512 float4, 2 per thread
#pragma unroll
        for (int i = 0; i < 2; i++) {
            int f = tid + i * 256;
            int m = f >> 2;
            int k4 = (f & 3) * 4;
            int gm = m0 + m;
            float4 v = make_float4(0.f, 0.f, 0.f, 0.f);
            float s = 0.f;
            if (gm < M) {
                v = *reinterpret_cast<const float4*>(A + (size_t)gm * K + k0 + k4);
                s = scale[gm];
            }
            As[m][k4 + 0] = v.x * s;
            As[m][k4 + 1] = v.y * s;
            As[m][k4 + 2] = v.z * s;
            As[m][k4 + 3] = v.w * s;
        }
        // load B tile: 512 float4, 2 per thread
#pragma unroll
        for (int i = 0; i < 2; i++) {
            int f = tid + i * 256;
            int kr = f >> 5;
            int c4 = (f & 31) * 4;
            float4 v = *reinterpret_cast<const float4*>(W + (size_t)(k0 + kr) * N + n0 + c4);
            *reinterpret_cast<float4*>(&Bs[kr][c4]) = v;
        }
        __syncthreads();

#pragma unroll
        for (int k = 0; k < BK; k++) {
            float a[8];
#pragma unroll
            for (int i = 0; i < 4; i++) {
                a[i]     = As[ty * 4 + i][k];
                a[4 + i] = As[64 + ty * 4 + i][k];
            }
            float4 b0 = *reinterpret_cast<const float4*>(&Bs[k][tx * 4]);
            float4 b1 = *reinterpret_cast<const float4*>(&Bs[k][64 + tx * 4]);
            unsigned long long bp[4];
            bp[0] = pack2(b0.x, b0.y);
            bp[1] = pack2(b0.z, b0.w);
            bp[2] = pack2(b1.x, b1.y);
            bp[3] = pack2(b1.z, b1.w);
#pragma unroll
            for (int i = 0; i < 8; i++) {
                unsigned long long a2 = pack2(a[i], a[i]);
                fma2(c2[i][0], a2, bp[0]);
                fma2(c2[i][1], a2, bp[1]);
                fma2(c2[i][2], a2, bp[2]);
                fma2(c2[i][3], a2, bp[3]);
            }
        }
        __syncthreads();
    }

#pragma unroll
    for (int i = 0; i < 8; i++) {
        int gm = m0 + ((i < 4) ? (ty * 4 + i) : (64 + ty * 4 + i - 4));
        if (gm < M) {
            float2 p0 = unpack2(c2[i][0]), p1 = unpack2(c2[i][1]);
            float2 p2 = unpack2(c2[i][2]), p3 = unpack2(c2[i][3]);
            float4 v0 = make_float4(p0.x, p0.y, p1.x, p1.y);
            float4 v1 = make_float4(p2.x, p2.y, p3.x, p3.y);
            *reinterpret_cast<float4*>(C + (size_t)gm * N + n0 + tx * 4) = v0;
            *reinterpret_cast<float4*>(C + (size_t)gm * N + n0 + 64 + tx * 4) = v1;
        }
    }
}

// --------------------------- CSR aggregation -------------------------------
// out[v,:] = act( (sum_{e in csr(v)} H[srt[e],:]) * rsqrt(max(deg,1)) + bias )
// One warp per destination node; float4 lanes.

__device__ __forceinline__ void acc4(float4& a, const float4& b) {
    a.x += b.x; a.y += b.y; a.z += b.z; a.w += b.w;
}

template <int F, bool RELU>
__global__ __launch_bounds__(256)
void agg_kernel(const float* __restrict__ H, const int* __restrict__ off,
                const int* __restrict__ srt, const float* __restrict__ bias,
                float* __restrict__ out, int n) {
    int warp = (blockIdx.x * blockDim.x + threadIdx.x) >> 5;
    int lane = threadIdx.x & 31;
    if (warp >= n) return;

    int s0 = off[warp], s1 = off[warp + 1];
    float4 acc0 = make_float4(0.f, 0.f, 0.f, 0.f);
    float4 acc1 = make_float4(0.f, 0.f, 0.f, 0.f);

    int e = s0;
    for (; e + 2 <= s1; e += 2) {
        int sA = __ldg(&srt[e]);
        int sB = __ldg(&srt[e + 1]);
        const float4* rA = reinterpret_cast<const float4*>(H + (size_t)sA * F);
        const float4* rB = reinterpret_cast<const float4*>(H + (size_t)sB * F);
        float4 vA0 = __ldg(rA + lane);
        float4 vB0 = __ldg(rB + lane);
        if (F == 256) {
            float4 vA1 = __ldg(rA + 32 + lane);
            float4 vB1 = __ldg(rB + 32 + lane);
            acc4(acc1, vA1); acc4(acc1, vB1);
        }
        acc4(acc0, vA0); acc4(acc0, vB0);
    }
    if (e < s1) {
        int sA = __ldg(&srt[e]);
        const float4* rA = reinterpret_cast<const float4*>(H + (size_t)sA * F);
        acc4(acc0, __ldg(rA + lane));
        if (F == 256) acc4(acc1, __ldg(rA + 32 + lane));
    }

    int deg = s1 - s0;
    float sc = rsqrtf((float)(deg > 0 ? deg : 1));
    const float4* bv = reinterpret_cast<const float4*>(bias);
    float4 b0 = __ldg(bv + lane);
    float4 r0;
    r0.x = acc0.x * sc + b0.x;
    r0.y = acc0.y * sc + b0.y;
    r0.z = acc0.z * sc + b0.z;
    r0.w = acc0.w * sc + b0.w;
    if (RELU) {
        r0.x = fmaxf(r0.x, 0.f); r0.y = fmaxf(r0.y, 0.f);
        r0.z = fmaxf(r0.z, 0.f); r0.w = fmaxf(r0.w, 0.f);
    }
    float4* ov = reinterpret_cast<float4*>(out + (size_t)warp * F);
    ov[lane] = r0;

    if (F == 256) {
        float4 b1 = __ldg(bv + 32 + lane);
        float4 r1;
        r1.x = acc1.x * sc + b1.x;
        r1.y = acc1.y * sc + b1.y;
        r1.z = acc1.z * sc + b1.z;
        r1.w = acc1.w * sc + b1.w;
        if (RELU) {
            r1.x = fmaxf(r1.x, 0.f); r1.y = fmaxf(r1.y, 0.f);
            r1.z = fmaxf(r1.z, 0.f); r1.w = fmaxf(r1.w, 0.f);
        }
        ov[32 + lane] = r1;
    }
}

// --------------------------------- launch ----------------------------------

extern "C" void kernel_launch(void* const* d_in, const int* in_sizes, int n_in,
                              void* d_out, int out_size) {
    const float* x_a    = (const float*)d_in[0];
    const float* x_b    = (const float*)d_in[1];
    const float* W1_bel = (const float*)d_in[2];
    const float* b1_bel = (const float*)d_in[3];
    const float* W1_inc = (const float*)d_in[4];
    const float* b1_inc = (const float*)d_in[5];
    const float* W2_bel = (const float*)d_in[6];
    const float* b2_bel = (const float*)d_in[7];
    const float* W2_inc = (const float*)d_in[8];
    const float* b2_inc = (const float*)d_in[9];
    const int* bel_src  = (const int*)d_in[10];
    const int* bel_dst  = (const int*)d_in[11];
    const int* inc_src  = (const int*)d_in[12];
    const int* inc_dst  = (const int*)d_in[13];

    const int HID     = in_sizes[3];             // 256
    const int INF     = in_sizes[2] / HID;       // 256
    const int BEL_OUT = in_sizes[7];             // 128
    const int INC_OUT = in_sizes[9];             // 128
    const int NA      = in_sizes[0] / INF;       // 50000
    const int NB      = in_sizes[1] / INF;       // 10000
    const int E       = in_sizes[10];            // 300000

    float* out_a = (float*)d_out;                      // [NA, INC_OUT]
    float* out_b = out_a + (size_t)NA * INC_OUT;       // [NB, BEL_OUT]

    // Resolve scratch symbol addresses (no allocation; safe during capture).
    float *h1a, *h1b, *ha, *hb, *h2a, *h2b, *scale_a, *scale_b;
    int *deg_a, *deg_b, *cnt_bel, *cnt_inc, *off_bel, *off_inc;
    int *cur_bel, *cur_inc, *srt_bel, *srt_inc, *partials;
    cudaGetSymbolAddress((void**)&h1a, g_h1a);
    cudaGetSymbolAddress((void**)&h1b, g_h1b);
    cudaGetSymbolAddress((void**)&ha,  g_ha);
    cudaGetSymbolAddress((void**)&hb,  g_hb);
    cudaGetSymbolAddress((void**)&h2a, g_h2a);
    cudaGetSymbolAddress((void**)&h2b, g_h2b);
    cudaGetSymbolAddress((void**)&scale_a, g_scale_a);
    cudaGetSymbolAddress((void**)&scale_b, g_scale_b);
    cudaGetSymbolAddress((void**)&deg_a, g_deg_a);
    cudaGetSymbolAddress((void**)&deg_b, g_deg_b);
    cudaGetSymbolAddress((void**)&cnt_bel, g_cnt_bel);
    cudaGetSymbolAddress((void**)&cnt_inc, g_cnt_inc);
    cudaGetSymbolAddress((void**)&off_bel, g_off_bel);
    cudaGetSymbolAddress((void**)&off_inc, g_off_inc);
    cudaGetSymbolAddress((void**)&cur_bel, g_cur_bel);
    cudaGetSymbolAddress((void**)&cur_inc, g_cur_inc);
    cudaGetSymbolAddress((void**)&srt_bel, g_srt_bel);
    cudaGetSymbolAddress((void**)&srt_inc, g_srt_inc);
    cudaGetSymbolAddress((void**)&partials, g_partials);

    const int TB = 256;
    const int gE = (E + TB - 1) / TB;

    // ---- degrees + scales ----
    cudaMemsetAsync(deg_a,   0, (size_t)NA * 4);
    cudaMemsetAsync(deg_b,   0, (size_t)NB * 4);
    cudaMemsetAsync(cnt_bel, 0, (size_t)NB * 4);
    cudaMemsetAsync(cnt_inc, 0, (size_t)NA * 4);
    count_kernel<<<gE, TB>>>(bel_src, deg_a, E);
    count_kernel<<<gE, TB>>>(inc_src, deg_b, E);
    count_kernel<<<gE, TB>>>(bel_dst, cnt_bel, E);
    count_kernel<<<gE, TB>>>(inc_dst, cnt_inc, E);
    scale_kernel<<<(NA + TB - 1) / TB, TB>>>(deg_a, scale_a, NA);
    scale_kernel<<<(NB + TB - 1) / TB, TB>>>(deg_b, scale_b, NB);

    // ---- CSR for bel (by dst over NB) ----
    {
        int nb = (NB + 1023) / 1024;
        scan_block<<<nb, 1024>>>(cnt_bel, off_bel, partials, NB);
        scan_partials<<<1, 32>>>(partials, nb);
        scan_add<<<(NB + TB - 1) / TB, TB>>>(off_bel, partials, NB, E);
        cudaMemcpyAsync(cur_bel, off_bel, (size_t)NB * 4, cudaMemcpyDeviceToDevice);
        fill_csr<<<gE, TB>>>(bel_src, bel_dst, E, cur_bel, srt_bel);
    }
    // ---- CSR for inc (by dst over NA) ----
    {
        int nb = (NA + 1023) / 1024;
        scan_block<<<nb, 1024>>>(cnt_inc, off_inc, partials, NA);
        scan_partials<<<1, 32>>>(partials, nb);
        scan_add<<<(NA + TB - 1) / TB, TB>>>(off_inc, partials, NA, E);
        cudaMemcpyAsync(cur_inc, off_inc, (size_t)NA * 4, cudaMemcpyDeviceToDevice);
        fill_csr<<<gE, TB>>>(inc_src, inc_dst, E, cur_inc, srt_inc);
    }

    // ---- layer 1 ----
    gemm_scaled<<<dim3(HID / 128, (NA + 127) / 128), 256>>>(x_a, scale_a, W1_bel, h1a, NA, HID, INF);
    gemm_scaled<<<dim3(HID / 128, (NB + 127) / 128), 256>>>(x_b, scale_b, W1_inc, h1b, NB, HID, INF);
    agg_kernel<256, true><<<(NB + 7) / 8, 256>>>(h1a, off_bel, srt_bel, b1_bel, hb, NB);
    agg_kernel<256, true><<<(NA + 7) / 8, 256>>>(h1b, off_inc, srt_inc, b1_inc, ha, NA);

    // ---- layer 2 ----
    gemm_scaled<<<dim3(BEL_OUT / 128, (NA + 127) / 128), 256>>>(ha, scale_a, W2_bel, h2a, NA, BEL_OUT, HID);
    gemm_scaled<<<dim3(INC_OUT / 128, (NB + 127) / 128), 256>>>(hb, scale_b, W2_inc, h2b, NB, INC_OUT, HID);
    agg_kernel<128, false><<<(NB + 7) / 8, 256>>>(h2a, off_bel, srt_bel, b2_bel, out_b, NB);
    agg_kernel<128, false><<<(NA + 7) / 8, 256>>>(h2b, off_inc, srt_inc, b2_inc, out_a, NA);
}

// round 17
// speedup vs baseline: 1.0084x; 1.0036x over previous
#include <cuda_runtime.h>
#include <cstdint>

// ---------------------------------------------------------------------------
// RGCN (2-layer bipartite GraphConv, norm='both') for fixed shapes:
//   N_A=50000, N_B=10000, E=300000, IN_F=HID=256, OUT=128
// Pipeline per call (all on default stream, graph-capturable):
//   degrees (atomics) -> row scales -> CSR-by-dst (scan + cursor fill)
//   GEMM1 (row-scaled)  -> agg+bias+relu   (layer 1, both directions)
//   GEMM2 (row-scaled)  -> agg+bias        (layer 2, both directions)
// GEMM uses 128x128x16 tiles with packed fma.rn.f32x2 accumulators.
// ---------------------------------------------------------------------------

#define NA_MAX 50000
#define NB_MAX 10000
#define E_MAX  300000

// Scratch (device globals; no allocation anywhere)
__device__ float g_h1a[NA_MAX * 256];   // (x_a*sA) @ W1_bel
__device__ float g_h1b[NB_MAX * 256];   // (x_b*sB) @ W1_inc
__device__ float g_ha [NA_MAX * 256];   // relu-aggregated layer-1 A features
__device__ float g_hb [NB_MAX * 256];   // relu-aggregated layer-1 B features
__device__ float g_h2a[NA_MAX * 128];   // (h_a*sA) @ W2_bel
__device__ float g_h2b[NB_MAX * 128];   // (h_b*sB) @ W2_inc

__device__ int   g_deg_a[NA_MAX];       // out-degree over bel_src
__device__ int   g_deg_b[NB_MAX];       // out-degree over inc_src
__device__ float g_scale_a[NA_MAX];     // rsqrt(max(deg_a,1))
__device__ float g_scale_b[NB_MAX];

__device__ int g_cnt_bel[NB_MAX];       // histogram of bel_dst
__device__ int g_cnt_inc[NA_MAX];       // histogram of inc_dst
__device__ int g_off_bel[NB_MAX + 1];
__device__ int g_off_inc[NA_MAX + 1];
__device__ int g_cur_bel[NB_MAX];
__device__ int g_cur_inc[NA_MAX];
__device__ int g_srt_bel[E_MAX];        // bel src ids sorted by dst
__device__ int g_srt_inc[E_MAX];        // inc src ids sorted by dst
__device__ int g_partials[128];

// ------------------------------ small kernels ------------------------------

__global__ void count_kernel(const int* __restrict__ idx, int* __restrict__ cnt, int n) {
    int i = blockIdx.x * blockDim.x + threadIdx.x;
    if (i < n) atomicAdd(&cnt[idx[i]], 1);
}

__global__ void scale_kernel(const int* __restrict__ deg, float* __restrict__ sc, int n) {
    int i = blockIdx.x * blockDim.x + threadIdx.x;
    if (i < n) {
        int d = deg[i];
        sc[i] = rsqrtf((float)(d > 0 ? d : 1));
    }
}

// Exclusive-scan stage 1: per-block Hillis-Steele, write block totals.
__global__ void scan_block(const int* __restrict__ cnt, int* __restrict__ off,
                           int* __restrict__ partials, int n) {
    __shared__ int s[1024];
    int i = blockIdx.x * 1024 + threadIdx.x;
    int v = (i < n) ? cnt[i] : 0;
    s[threadIdx.x] = v;
    __syncthreads();
#pragma unroll
    for (int d = 1; d < 1024; d <<= 1) {
        int t = (threadIdx.x >= d) ? s[threadIdx.x - d] : 0;
        __syncthreads();
        s[threadIdx.x] += t;
        __syncthreads();
    }
    if (i < n) off[i] = s[threadIdx.x] - v;           // exclusive within block
    if (threadIdx.x == 1023) partials[blockIdx.x] = s[1023];
}

__global__ void scan_partials(int* partials, int nb) {
    if (threadIdx.x == 0 && blockIdx.x == 0) {
        int acc = 0;
        for (int b = 0; b < nb; b++) { int t = partials[b]; partials[b] = acc; acc += t; }
    }
}

__global__ void scan_add(int* __restrict__ off, const int* __restrict__ partials,
                         int n, int total) {
    int i = blockIdx.x * blockDim.x + threadIdx.x;
    if (i < n) off[i] += partials[i >> 10];
    if (i == 0) off[n] = total;
}

__global__ void fill_csr(const int* __restrict__ src, const int* __restrict__ dst, int n,
                         int* __restrict__ cursor, int* __restrict__ srt) {
    int e = blockIdx.x * blockDim.x + threadIdx.x;
    if (e < n) {
        int p = atomicAdd(&cursor[dst[e]], 1);
        srt[p] = src[e];
    }
}

// ------------------------------ GEMM (f32x2) -------------------------------
// C[M,N] = diag(scale) * A[M,K] @ W[K,N].  N % 128 == 0, K % 16 == 0.

__device__ __forceinline__ unsigned long long pack2(float x, float y) {
    unsigned long long r;
    asm("mov.b64 %0, {%1, %2};" : "=l"(r) : "f"(x), "f"(y));
    return r;
}
__device__ __forceinline__ void fma2(unsigned long long& c, unsigned long long a,
                                     unsigned long long b) {
    asm("fma.rn.f32x2 %0, %1, %2, %0;" : "+l"(c) : "l"(a), "l"(b));
}
__device__ __forceinline__ float2 unpack2(unsigned long long v) {
    float2 r;
    asm("mov.b64 {%0, %1}, %2;" : "=f"(r.x), "=f"(r.y) : "l"(v));
    return r;
}

__global__ __launch_bounds__(256)
void gemm_scaled(const float* __restrict__ A, const float* __restrict__ scale,
                 const float* __restrict__ W, float* __restrict__ C,
                 int M, int N, int K) {
    constexpr int BM = 128, BN = 128, BK = 16;
    __shared__ float As[BM][BK + 4];   // row stride 20 floats
    __shared__ float Bs[BK][BN];

    int tid = threadIdx.x;
    int tx = tid & 15, ty = tid >> 4;
    int m0 = blockIdx.y * BM;
    int n0 = blockIdx.x * BN;

    unsigned long long c2[8][4];
#pragma unroll
    for (int i = 0; i < 8; i++)
#pragma unroll
        for (int j = 0; j < 4; j++) c2[i][j] = 0ull;

    for (int k0 = 0; k0 < K; k0 += BK) {
        // load A tile (row-scaled): 512 float4, 2 per thread
#pragma unroll
        for (int i = 0; i < 2; i++) {
            int f = tid + i * 256;
            int m = f >> 2;
            int k4 = (f & 3) * 4;
            int gm = m0 + m;
            float4 v = make_float4(0.f, 0.f, 0.f, 0.f);
            float s = 0.f;
            if (gm < M) {
                v = *reinterpret_cast<const float4*>(A + (size_t)gm * K + k0 + k4);
                s = scale[gm];
            }
            As[m][k4 + 0] = v.x * s;
            As[m][k4 + 1] = v.y * s;
            As[m][k4 + 2] = v.z * s;
            As[m][k4 + 3] = v.w * s;
        }
        // load B tile: 512 float4, 2 per thread
#pragma unroll
        for (int i = 0; i < 2; i++) {
            int f = tid + i * 256;
            int kr = f >> 5;
            int c4 = (f & 31) * 4;
            float4 v = *reinterpret_cast<const float4*>(W + (size_t)(k0 + kr) * N + n0 + c4);
            *reinterpret_cast<float4*>(&Bs[kr][c4]) = v;
        }
        __syncthreads();

#pragma unroll
        for (int k = 0; k < BK; k++) {
            float a[8];
#pragma unroll
            for (int i = 0; i < 4; i++) {
                a[i]     = As[ty * 4 + i][k];
                a[4 + i] = As[64 + ty * 4 + i][k];
            }
            float4 b0 = *reinterpret_cast<const float4*>(&Bs[k][tx * 4]);
            float4 b1 = *reinterpret_cast<const float4*>(&Bs[k][64 + tx * 4]);
            unsigned long long bp[4];
            bp[0] = pack2(b0.x, b0.y);
            bp[1] = pack2(b0.z, b0.w);
            bp[2] = pack2(b1.x, b1.y);
            bp[3] = pack2(b1.z, b1.w);
#pragma unroll
            for (int i = 0; i < 8; i++) {
                unsigned long long a2 = pack2(a[i], a[i]);
                fma2(c2[i][0], a2, bp[0]);
                fma2(c2[i][1], a2, bp[1]);
                fma2(c2[i][2], a2, bp[2]);
                fma2(c2[i][3], a2, bp[3]);
            }
        }
        __syncthreads();
    }

#pragma unroll
    for (int i = 0; i < 8; i++) {
        int gm = m0 + ((i < 4) ? (ty * 4 + i) : (64 + ty * 4 + i - 4));
        if (gm < M) {
            float2 p0 = unpack2(c2[i][0]), p1 = unpack2(c2[i][1]);
            float2 p2 = unpack2(c2[i][2]), p3 = unpack2(c2[i][3]);
            float4 v0 = make_float4(p0.x, p0.y, p1.x, p1.y);
            float4 v1 = make_float4(p2.x, p2.y, p3.x, p3.y);
            *reinterpret_cast<float4*>(C + (size_t)gm * N + n0 + tx * 4) = v0;
            *reinterpret_cast<float4*>(C + (size_t)gm * N + n0 + 64 + tx * 4) = v1;
        }
    }
}

// --------------------------- CSR aggregation -------------------------------
// out[v,:] = act( (sum_{e in csr(v)} H[srt[e],:]) * rsqrt(max(deg,1)) + bias )
// One warp per destination node; float4 lanes.

__device__ __forceinline__ void acc4(float4& a, const float4& b) {
    a.x += b.x; a.y += b.y; a.z += b.z; a.w += b.w;
}

template <int F, bool RELU>
__global__ __launch_bounds__(256)
void agg_kernel(const float* __restrict__ H, const int* __restrict__ off,
                const int* __restrict__ srt, const float* __restrict__ bias,
                float* __restrict__ out, int n) {
    int warp = (blockIdx.x * blockDim.x + threadIdx.x) >> 5;
    int lane = threadIdx.x & 31;
    if (warp >= n) return;

    int s0 = off[warp], s1 = off[warp + 1];
    float4 acc0 = make_float4(0.f, 0.f, 0.f, 0.f);
    float4 acc1 = make_float4(0.f, 0.f, 0.f, 0.f);

    int e = s0;
    for (; e + 2 <= s1; e += 2) {
        int sA = __ldg(&srt[e]);
        int sB = __ldg(&srt[e + 1]);
        const float4* rA = reinterpret_cast<const float4*>(H + (size_t)sA * F);
        const float4* rB = reinterpret_cast<const float4*>(H + (size_t)sB * F);
        float4 vA0 = __ldg(rA + lane);
        float4 vB0 = __ldg(rB + lane);
        if (F == 256) {
            float4 vA1 = __ldg(rA + 32 + lane);
            float4 vB1 = __ldg(rB + 32 + lane);
            acc4(acc1, vA1); acc4(acc1, vB1);
        }
        acc4(acc0, vA0); acc4(acc0, vB0);
    }
    if (e < s1) {
        int sA = __ldg(&srt[e]);
        const float4* rA = reinterpret_cast<const float4*>(H + (size_t)sA * F);
        acc4(acc0, __ldg(rA + lane));
        if (F == 256) acc4(acc1, __ldg(rA + 32 + lane));
    }

    int deg = s1 - s0;
    float sc = rsqrtf((float)(deg > 0 ? deg : 1));
    const float4* bv = reinterpret_cast<const float4*>(bias);
    float4 b0 = __ldg(bv + lane);
    float4 r0;
    r0.x = acc0.x * sc + b0.x;
    r0.y = acc0.y * sc + b0.y;
    r0.z = acc0.z * sc + b0.z;
    r0.w = acc0.w * sc + b0.w;
    if (RELU) {
        r0.x = fmaxf(r0.x, 0.f); r0.y = fmaxf(r0.y, 0.f);
        r0.z = fmaxf(r0.z, 0.f); r0.w = fmaxf(r0.w, 0.f);
    }
    float4* ov = reinterpret_cast<float4*>(out + (size_t)warp * F);
    ov[lane] = r0;

    if (F == 256) {
        float4 b1 = __ldg(bv + 32 + lane);
        float4 r1;
        r1.x = acc1.x * sc + b1.x;
        r1.y = acc1.y * sc + b1.y;
        r1.z = acc1.z * sc + b1.z;
        r1.w = acc1.w * sc + b1.w;
        if (RELU) {
            r1.x = fmaxf(r1.x, 0.f); r1.y = fmaxf(r1.y, 0.f);
            r1.z = fmaxf(r1.z, 0.f); r1.w = fmaxf(r1.w, 0.f);
        }
        ov[32 + lane] = r1;
    }
}

// --------------------------------- launch ----------------------------------

extern "C" void kernel_launch(void* const* d_in, const int* in_sizes, int n_in,
                              void* d_out, int out_size) {
    const float* x_a    = (const float*)d_in[0];
    const float* x_b    = (const float*)d_in[1];
    const float* W1_bel = (const float*)d_in[2];
    const float* b1_bel = (const float*)d_in[3];
    const float* W1_inc = (const float*)d_in[4];
    const float* b1_inc = (const float*)d_in[5];
    const float* W2_bel = (const float*)d_in[6];
    const float* b2_bel = (const float*)d_in[7];
    const float* W2_inc = (const float*)d_in[8];
    const float* b2_inc = (const float*)d_in[9];
    const int* bel_src  = (const int*)d_in[10];
    const int* bel_dst  = (const int*)d_in[11];
    const int* inc_src  = (const int*)d_in[12];
    const int* inc_dst  = (const int*)d_in[13];

    const int HID     = in_sizes[3];             // 256
    const int INF     = in_sizes[2] / HID;       // 256
    const int BEL_OUT = in_sizes[7];             // 128
    const int INC_OUT = in_sizes[9];             // 128
    const int NA      = in_sizes[0] / INF;       // 50000
    const int NB      = in_sizes[1] / INF;       // 10000
    const int E       = in_sizes[10];            // 300000

    float* out_a = (float*)d_out;                      // [NA, INC_OUT]
    float* out_b = out_a + (size_t)NA * INC_OUT;       // [NB, BEL_OUT]

    // Resolve scratch symbol addresses (no allocation; safe during capture).
    float *h1a, *h1b, *ha, *hb, *h2a, *h2b, *scale_a, *scale_b;
    int *deg_a, *deg_b, *cnt_bel, *cnt_inc, *off_bel, *off_inc;
    int *cur_bel, *cur_inc, *srt_bel, *srt_inc, *partials;
    cudaGetSymbolAddress((void**)&h1a, g_h1a);
    cudaGetSymbolAddress((void**)&h1b, g_h1b);
    cudaGetSymbolAddress((void**)&ha,  g_ha);
    cudaGetSymbolAddress((void**)&hb,  g_hb);
    cudaGetSymbolAddress((void**)&h2a, g_h2a);
    cudaGetSymbolAddress((void**)&h2b, g_h2b);
    cudaGetSymbolAddress((void**)&scale_a, g_scale_a);
    cudaGetSymbolAddress((void**)&scale_b, g_scale_b);
    cudaGetSymbolAddress((void**)&deg_a, g_deg_a);
    cudaGetSymbolAddress((void**)&deg_b, g_deg_b);
    cudaGetSymbolAddress((void**)&cnt_bel, g_cnt_bel);
    cudaGetSymbolAddress((void**)&cnt_inc, g_cnt_inc);
    cudaGetSymbolAddress((void**)&off_bel, g_off_bel);
    cudaGetSymbolAddress((void**)&off_inc, g_off_inc);
    cudaGetSymbolAddress((void**)&cur_bel, g_cur_bel);
    cudaGetSymbolAddress((void**)&cur_inc, g_cur_inc);
    cudaGetSymbolAddress((void**)&srt_bel, g_srt_bel);
    cudaGetSymbolAddress((void**)&srt_inc, g_srt_inc);
    cudaGetSymbolAddress((void**)&partials, g_partials);

    const int TB = 256;
    const int gE = (E + TB - 1) / TB;

    // ---- degrees + scales ----
    cudaMemsetAsync(deg_a,   0, (size_t)NA * 4);
    cudaMemsetAsync(deg_b,   0, (size_t)NB * 4);
    cudaMemsetAsync(cnt_bel, 0, (size_t)NB * 4);
    cudaMemsetAsync(cnt_inc, 0, (size_t)NA * 4);
    count_kernel<<<gE, TB>>>(bel_src, deg_a, E);
    count_kernel<<<gE, TB>>>(inc_src, deg_b, E);
    count_kernel<<<gE, TB>>>(bel_dst, cnt_bel, E);
    count_kernel<<<gE, TB>>>(inc_dst, cnt_inc, E);
    scale_kernel<<<(NA + TB - 1) / TB, TB>>>(deg_a, scale_a, NA);
    scale_kernel<<<(NB + TB - 1) / TB, TB>>>(deg_b, scale_b, NB);

    // ---- CSR for bel (by dst over NB) ----
    {
        int nb = (NB + 1023) / 1024;
        scan_block<<<nb, 1024>>>(cnt_bel, off_bel, partials, NB);
        scan_partials<<<1, 32>>>(partials, nb);
        scan_add<<<(NB + TB - 1) / TB, TB>>>(off_bel, partials, NB, E);
        cudaMemcpyAsync(cur_bel, off_bel, (size_t)NB * 4, cudaMemcpyDeviceToDevice);
        fill_csr<<<gE, TB>>>(bel_src, bel_dst, E, cur_bel, srt_bel);
    }
    // ---- CSR for inc (by dst over NA) ----
    {
        int nb = (NA + 1023) / 1024;
        scan_block<<<nb, 1024>>>(cnt_inc, off_inc, partials, NA);
        scan_partials<<<1, 32>>>(partials, nb);
        scan_add<<<(NA + TB - 1) / TB, TB>>>(off_inc, partials, NA, E);
        cudaMemcpyAsync(cur_inc, off_inc, (size_t)NA * 4, cudaMemcpyDeviceToDevice);
        fill_csr<<<gE, TB>>>(inc_src, inc_dst, E, cur_inc, srt_inc);
    }

    // ---- layer 1 ----
    gemm_scaled<<<dim3(HID / 128, (NA + 127) / 128), 256>>>(x_a, scale_a, W1_bel, h1a, NA, HID, INF);
    gemm_scaled<<<dim3(HID / 128, (NB + 127) / 128), 256>>>(x_b, scale_b, W1_inc, h1b, NB, HID, INF);
    agg_kernel<256, true><<<(NB + 7) / 8, 256>>>(h1a, off_bel, srt_bel, b1_bel, hb, NB);
    agg_kernel<256, true><<<(NA + 7) / 8, 256>>>(h1b, off_inc, srt_inc, b1_inc, ha, NA);

    // ---- layer 2 ----
    gemm_scaled<<<dim3(BEL_OUT / 128, (NA + 127) / 128), 256>>>(ha, scale_a, W2_bel, h2a, NA, BEL_OUT, HID);
    gemm_scaled<<<dim3(INC_OUT / 128, (NB + 127) / 128), 256>>>(hb, scale_b, W2_inc, h2b, NB, INC_OUT, HID);
    agg_kernel<128, false><<<(NB + 7) / 8, 256>>>(h2a, off_bel, srt_bel, b2_bel, out_b, NB);
    agg_kernel<128, false><<<(NA + 7) / 8, 256>>>(h2b, off_inc, srt_inc, b2_inc, out_a, NA);
}